// round 11
// baseline (speedup 1.0000x reference)
#include <cuda_runtime.h>
#include <cstdint>
#include <cstddef>

#define NN 20000
#define NE 320000
#define ALPHA 0.2f

// ---------------- scratch (device globals; no allocation allowed) ------------
__device__ __align__(16) float g_B1[64 * 1024];
__device__ __align__(16) float g_B2[1024 * 1024];
__device__ __align__(16) float g_B3[1024 * 768];
__device__ __align__(16) float g_Wh[(size_t)NN * 1024];
__device__ __align__(16) float g_x1[(size_t)NN * 1024];
__device__ __align__(16) float g_x2[(size_t)NN * 1024];
__device__ __align__(16) float g_h[(size_t)NN * 1024];
__device__ __align__(16) float g_xp[(size_t)NN * 64];
__device__ __align__(16) float g_ssrc[3 * 6 * NN];
__device__ __align__(16) float g_sdst[3 * 6 * NN];
__device__ __align__(16) int g_srcI[NE];
__device__ __align__(16) int g_dstI[NE];
__device__ __align__(16) int g_cnt[NN];
__device__ __align__(16) int g_rowptr[NN + 4];
__device__ __align__(16) int g_cursor[NN];
__device__ __align__(16) int g_csrSrc[NE];
__device__ int g_is64;

// ---------------- helpers ----------------------------------------------------
__device__ __forceinline__ float eluf(float z) { return z > 0.f ? z : expm1f(z); }
__device__ __forceinline__ float lrelu(float v) { return v > 0.f ? v : ALPHA * v; }
__device__ __forceinline__ unsigned smem_u32(const void* p) {
    return (unsigned)__cvta_generic_to_shared(p);
}
__device__ __forceinline__ void cp16(unsigned dst, const void* src, int szbytes) {
    asm volatile("cp.async.cg.shared.global [%0], [%1], 16, %2;"
                 :: "r"(dst), "l"(src), "r"(szbytes));
}
__device__ __forceinline__ void cp_commit() { asm volatile("cp.async.commit_group;"); }
template <int NWAIT>
__device__ __forceinline__ void cp_wait() {
    asm volatile("cp.async.wait_group %0;" :: "n"(NWAIT));
}

// ---------------- setup kernels -----------------------------------------------
__global__ void detect_k(const void* __restrict__ ei, int N) {
    __shared__ int bad;
    if (threadIdx.x == 0) bad = 0;
    __syncthreads();
    long long v = ((const long long*)ei)[threadIdx.x];
    if (v < 0 || v >= N) bad = 1;
    __syncthreads();
    if (threadIdx.x == 0) g_is64 = !bad;
}
// zero cnt + score buffers, pad x -> xp, all in one grid
__global__ void setup_k(const float* __restrict__ x, float* __restrict__ xp,
                        int* __restrict__ cnt, float* __restrict__ ssrc,
                        float* __restrict__ sdst) {
    int i = blockIdx.x * blockDim.x + threadIdx.x;
    if (i < NN) cnt[i] = 0;
    if (i < 3 * 6 * NN) { ssrc[i] = 0.f; sdst[i] = 0.f; }
    if (i < NN * 64) {
        int n = i >> 6, c = i & 63;
        xp[i] = (c < 50) ? x[n * 50 + c] : 0.f;
    }
}
__global__ void convhist_k(const void* __restrict__ ei, int* __restrict__ s,
                           int* __restrict__ d, int* __restrict__ cnt, int E) {
    int i = blockIdx.x * blockDim.x + threadIdx.x;
    if (i >= E) return;
    int sv, dv;
    if (g_is64) {
        const long long* p = (const long long*)ei;
        sv = (int)p[i]; dv = (int)p[E + i];
    } else {
        const int* p = (const int*)ei;
        sv = p[i]; dv = p[E + i];
    }
    s[i] = sv; d[i] = dv;
    atomicAdd(&cnt[dv], 1);
}
// one-pass blocked scan: 1024 threads x 20 elements each
#define CPT 20
__global__ void scan_k(const int* __restrict__ cnt, int* __restrict__ rowptr,
                       int* __restrict__ cursor, int n) {
    __shared__ int sums[32];
    const int t = threadIdx.x;
    const int lane = t & 31, wid = t >> 5;
    const int base = t * CPT;
    int v[CPT];
    int tot = 0;
#pragma unroll
    for (int j = 0; j < CPT; j++) {
        v[j] = (base + j < n) ? cnt[base + j] : 0;
        tot += v[j];
    }
    int x = tot;
#pragma unroll
    for (int o = 1; o < 32; o <<= 1) {
        int y = __shfl_up_sync(0xffffffffu, x, o);
        if (lane >= o) x += y;
    }
    if (lane == 31) sums[wid] = x;
    __syncthreads();
    if (wid == 0) {
        int s = sums[lane];
#pragma unroll
        for (int o = 1; o < 32; o <<= 1) {
            int y = __shfl_up_sync(0xffffffffu, s, o);
            if (lane >= o) s += y;
        }
        sums[lane] = s;
    }
    __syncthreads();
    int run = (x - tot) + (wid ? sums[wid - 1] : 0);   // exclusive prefix
    if (t == 0) rowptr[0] = 0;
#pragma unroll
    for (int j = 0; j < CPT; j++) {
        int idx = base + j;
        if (idx < n) {
            cursor[idx] = run;
            run += v[j];
            rowptr[idx + 1] = run;
        }
    }
}
__global__ void fill_k(const int* __restrict__ src, const int* __restrict__ dst,
                       int* __restrict__ cursor, int* __restrict__ csrSrc, int E) {
    int i = blockIdx.x * blockDim.x + threadIdx.x;
    if (i >= E) return;
    int pos = atomicAdd(&cursor[dst[i]], 1);
    csrSrc[pos] = src[i];
}
// all three weight repacks in one launch
__global__ void repackall_k(const float* __restrict__ W1, const float* __restrict__ W2,
                            const float* __restrict__ W3, float* __restrict__ B1,
                            float* __restrict__ B2, float* __restrict__ B3) {
    const int T1 = 64 * 1024, T2 = 1024 * 1024, T3 = 1024 * 768;
    int i = blockIdx.x * blockDim.x + threadIdx.x;
    if (i < T1) {
        int k = i >> 10, rem = i & 1023, h = rem >> 8, f = rem & 255;
        B1[i] = (k < 50) ? W1[((size_t)h * 50 + k) * 256 + f] : 0.f;
    } else if (i < T1 + T2) {
        int j = i - T1;
        int k = j >> 10, rem = j & 1023, h = rem >> 8, f = rem & 255;
        B2[j] = W2[((size_t)h * 1024 + k) * 256 + f];
    } else if (i < T1 + T2 + T3) {
        int j = i - T1 - T2;
        int k = j / 768, rem = j - k * 768, h = rem >> 7, f = rem & 127;
        B3[j] = (f < 121) ? W3[((size_t)h * 1024 + k) * 121 + f] : 0.f;
    }
}

// ---------------- TF32 GEMM, GBK=32, 3-stage cp.async, fused scores -----------
#define GBM 128
#define GBN 128
#define GBK 32
#define APAD 36    // 144B row stride (9x16B)
#define BPAD 136   // 544B row stride (34x16B)
#define AS_WORDS (GBM * APAD)              // 4608
#define BS_WORDS (GBK * BPAD)              // 4352
#define STAGE_WORDS (AS_WORDS + BS_WORDS)  // 8960 (35840 B)
#define GEMM_SMEM (3 * STAGE_WORDS * 4)    // 107520 B

__global__ __launch_bounds__(256) void gemm_tf32(int M, int N, int K,
                                                 const float* __restrict__ A,
                                                 const float* __restrict__ B,
                                                 float* __restrict__ C,
                                                 const float* __restrict__ aVec,
                                                 int F, int hs, int astride,
                                                 float* __restrict__ ssrc,
                                                 float* __restrict__ sdst) {
    extern __shared__ float sm[];

    const int tid = threadIdx.x;
    const int warp = tid >> 5;
    const int lane = tid & 31;
    const int g = lane >> 2;
    const int tig = lane & 3;
    const int wm = warp & 1;
    const int wn = warp >> 1;
    const int bm = blockIdx.y * GBM;
    const int bn = blockIdx.x * GBN;

    float acc[4][4][4];
#pragma unroll
    for (int mf = 0; mf < 4; mf++)
#pragma unroll
        for (int nf = 0; nf < 4; nf++)
#pragma unroll
            for (int r = 0; r < 4; r++) acc[mf][nf][r] = 0.f;

    const int KT = K / GBK;

    // copy maps: A tile 128x32 words -> 1024 cp16 (4/thread); B tile 32x128 -> same
    auto issue = [&](int kt, int stg) {
        float* As = sm + stg * STAGE_WORDS;
        float* Bs = As + AS_WORDS;
        const int k0 = kt * GBK;
#pragma unroll
        for (int i = 0; i < 4; i++) {
            int c = tid + i * 256;
            int arow = c >> 3, akoff = (c & 7) * 4;
            cp16(smem_u32(As + arow * APAD + akoff),
                 A + (size_t)(bm + arow) * K + k0 + akoff,
                 (bm + arow < M) ? 16 : 0);
            int brow = c >> 5, bcoff = (c & 31) * 4;
            cp16(smem_u32(Bs + brow * BPAD + bcoff),
                 B + (size_t)(k0 + brow) * N + bn + bcoff, 16);
        }
    };

    issue(0, 0); cp_commit();
    if (KT > 1) issue(1, 1);
    cp_commit();

    int stg = 0, stg2 = (KT > 2) ? 2 : (KT == 2 ? 0 : 1);
    for (int kt = 0; kt < KT; kt++) {
        cp_wait<1>();
        __syncthreads();
        if (kt + 2 < KT) issue(kt + 2, stg2);
        cp_commit();

        const float* As = sm + stg * STAGE_WORDS;
        const float* Bs = As + AS_WORDS;
#pragma unroll
        for (int ks = 0; ks < 4; ks++) {
            const int kc = ks * 8;
            unsigned af[4][4], bf[4][2];
#pragma unroll
            for (int mf = 0; mf < 4; mf++) {
                int r = wm * 64 + mf * 16;
                af[mf][0] = __float_as_uint(As[(r + g) * APAD + kc + tig]);
                af[mf][1] = __float_as_uint(As[(r + g + 8) * APAD + kc + tig]);
                af[mf][2] = __float_as_uint(As[(r + g) * APAD + kc + tig + 4]);
                af[mf][3] = __float_as_uint(As[(r + g + 8) * APAD + kc + tig + 4]);
            }
#pragma unroll
            for (int nf = 0; nf < 4; nf++) {
                int c = wn * 32 + nf * 8 + g;
                bf[nf][0] = __float_as_uint(Bs[(kc + tig) * BPAD + c]);
                bf[nf][1] = __float_as_uint(Bs[(kc + tig + 4) * BPAD + c]);
            }
#pragma unroll
            for (int mf = 0; mf < 4; mf++)
#pragma unroll
                for (int nf = 0; nf < 4; nf++) {
                    asm volatile(
                        "mma.sync.aligned.m16n8k8.row.col.f32.tf32.tf32.f32 "
                        "{%0,%1,%2,%3}, {%4,%5,%6,%7}, {%8,%9}, {%0,%1,%2,%3};"
                        : "+f"(acc[mf][nf][0]), "+f"(acc[mf][nf][1]),
                          "+f"(acc[mf][nf][2]), "+f"(acc[mf][nf][3])
                        : "r"(af[mf][0]), "r"(af[mf][1]), "r"(af[mf][2]), "r"(af[mf][3]),
                          "r"(bf[nf][0]), "r"(bf[nf][1]));
                }
        }
        stg = (stg + 1 == 3) ? 0 : stg + 1;
        stg2 = (stg2 + 1 == 3) ? 0 : stg2 + 1;
    }

    // ---- store C ----
#pragma unroll
    for (int mf = 0; mf < 4; mf++) {
        int r0 = bm + wm * 64 + mf * 16 + g;
#pragma unroll
        for (int nf = 0; nf < 4; nf++) {
            int c0 = bn + wn * 32 + nf * 8 + tig * 2;
            if (r0 < M) {
                float2 v = make_float2(acc[mf][nf][0], acc[mf][nf][1]);
                *(float2*)(C + (size_t)r0 * N + c0) = v;
            }
            if (r0 + 8 < M) {
                float2 v = make_float2(acc[mf][nf][2], acc[mf][nf][3]);
                *(float2*)(C + (size_t)(r0 + 8) * N + c0) = v;
            }
        }
    }

    // ---- fused attention-score partial dot ----
    {
        const int h0 = bn / hs;
        const int cbase = bn % hs;
        const float* av = aVec + (size_t)h0 * astride;
        float as_[8], ad_[8];
#pragma unroll
        for (int nf = 0; nf < 4; nf++)
#pragma unroll
            for (int e = 0; e < 2; e++) {
                int cf = cbase + wn * 32 + nf * 8 + tig * 2 + e;
                bool ok = cf < F;
                as_[nf * 2 + e] = ok ? av[cf] : 0.f;
                ad_[nf * 2 + e] = ok ? av[F + cf] : 0.f;
            }
#pragma unroll
        for (int mf = 0; mf < 4; mf++) {
            float s0 = 0.f, d0 = 0.f, s1 = 0.f, d1 = 0.f;
#pragma unroll
            for (int nf = 0; nf < 4; nf++)
#pragma unroll
                for (int e = 0; e < 2; e++) {
                    int idx = nf * 2 + e;
                    s0 += acc[mf][nf][e] * as_[idx];
                    d0 += acc[mf][nf][e] * ad_[idx];
                    s1 += acc[mf][nf][2 + e] * as_[idx];
                    d1 += acc[mf][nf][2 + e] * ad_[idx];
                }
#pragma unroll
            for (int o = 1; o <= 2; o <<= 1) {
                s0 += __shfl_xor_sync(0xffffffffu, s0, o);
                d0 += __shfl_xor_sync(0xffffffffu, d0, o);
                s1 += __shfl_xor_sync(0xffffffffu, s1, o);
                d1 += __shfl_xor_sync(0xffffffffu, d1, o);
            }
            if (tig == 0) {
                int r0 = bm + wm * 64 + mf * 16 + g;
                if (r0 < M) {
                    atomicAdd(&ssrc[h0 * NN + r0], s0);
                    atomicAdd(&sdst[h0 * NN + r0], d0);
                }
                if (r0 + 8 < M) {
                    atomicAdd(&ssrc[h0 * NN + r0 + 8], s1);
                    atomicAdd(&sdst[h0 * NN + r0 + 8], d1);
                }
            }
        }
    }
}

// ---------------- fused online-softmax + gather aggregation + epilogue --------
__global__ void agg_k(int N, int H, int F4, int ld, int hs, int outld, int ouths,
                      int mode,
                      const int* __restrict__ rowptr, const int* __restrict__ csrSrc,
                      const float* __restrict__ ssrc, const float* __restrict__ sdst,
                      const float* __restrict__ Wh, const float* __restrict__ xskip,
                      float* __restrict__ out) {
    int gw = (blockIdx.x * blockDim.x + threadIdx.x) >> 5;
    if (gw >= N * H) return;
    int lane = threadIdx.x & 31;
    int d = gw / H, h = gw - d * H;
    int start = rowptr[d], end = rowptr[d + 1];
    float sd = sdst[h * N + d];
    const float* ss = ssrc + (size_t)h * N;

    float m = -1e30f, s = 0.f;
    for (int i = start + lane; i < end; i += 32) {
        float v = lrelu(ss[csrSrc[i]] + sd);
        if (v > m) { s = s * __expf(m - v) + 1.f; m = v; }
        else s += __expf(v - m);
    }
#pragma unroll
    for (int o = 16; o; o >>= 1) {
        float mo = __shfl_xor_sync(0xffffffffu, m, o);
        float so = __shfl_xor_sync(0xffffffffu, s, o);
        float M = fmaxf(m, mo);
        s = s * __expf(m - M) + so * __expf(mo - M);
        m = M;
    }
    float inv = 1.f / (s + 1e-16f);

    float4 a0 = make_float4(0.f, 0.f, 0.f, 0.f);
    float4 a1 = make_float4(0.f, 0.f, 0.f, 0.f);
#pragma unroll 2
    for (int i = start; i < end; i++) {
        int sidx = csrSrc[i];
        float w = __expf(lrelu(ss[sidx] + sd) - m) * inv;
        const float4* rp = (const float4*)(Wh + (size_t)sidx * ld + h * hs);
        float4 u = rp[lane];
        a0.x += w * u.x; a0.y += w * u.y; a0.z += w * u.z; a0.w += w * u.w;
        if (F4 == 2) {
            float4 u2 = rp[lane + 32];
            a1.x += w * u2.x; a1.y += w * u2.y; a1.z += w * u2.z; a1.w += w * u2.w;
        }
    }

    size_t obase = (size_t)d * outld + h * ouths;
    if (mode == 1) {
        a0.x = eluf(eluf(a0.x)); a0.y = eluf(eluf(a0.y));
        a0.z = eluf(eluf(a0.z)); a0.w = eluf(eluf(a0.w));
        a1.x = eluf(eluf(a1.x)); a1.y = eluf(eluf(a1.y));
        a1.z = eluf(eluf(a1.z)); a1.w = eluf(eluf(a1.w));
    } else if (mode == 2) {
        const float4* xp = (const float4*)(xskip + obase);
        float4 p0 = xp[lane];
        a0.x = eluf(eluf(a0.x) + p0.x); a0.y = eluf(eluf(a0.y) + p0.y);
        a0.z = eluf(eluf(a0.z) + p0.z); a0.w = eluf(eluf(a0.w) + p0.w);
        if (F4 == 2) {
            float4 p1 = xp[lane + 32];
            a1.x = eluf(eluf(a1.x) + p1.x); a1.y = eluf(eluf(a1.y) + p1.y);
            a1.z = eluf(eluf(a1.z) + p1.z); a1.w = eluf(eluf(a1.w) + p1.w);
        }
    }
    float4* op = (float4*)(out + obase);
    op[lane] = a0;
    if (F4 == 2) op[lane + 32] = a1;
}

// ---------------- final: mean over 6 heads + sigmoid --------------------------
__global__ void final_k(const float* __restrict__ h3, float* __restrict__ out, int N) {
    int i = blockIdx.x * blockDim.x + threadIdx.x;
    if (i >= N * 121) return;
    int n = i / 121, f = i - n * 121;
    const float* base = h3 + (size_t)n * 768 + f;
    float v = 0.f;
#pragma unroll
    for (int h = 0; h < 6; h++) v += base[h * 128];
    v *= (1.f / 6.f);
    out[i] = 1.f / (1.f + __expf(-v));
}

// ---------------- driver ------------------------------------------------------
extern "C" void kernel_launch(void* const* d_in, const int* in_sizes, int n_in,
                              void* d_out, int out_size) {
    const float* x = (const float*)d_in[0];
    const void* ei = d_in[1];
    const float* W1 = (const float*)d_in[2];
    const float* a1 = (const float*)d_in[3];
    const float* W2 = (const float*)d_in[4];
    const float* a2 = (const float*)d_in[5];
    const float* W3 = (const float*)d_in[6];
    const float* a3 = (const float*)d_in[7];
    float* out = (float*)d_out;

    float *B1, *B2, *B3, *Wh, *x1, *x2, *hb, *xp, *ssrc, *sdst;
    int *srcI, *dstI, *cnt, *rowptr, *cursor, *csrSrc;
    cudaGetSymbolAddress((void**)&B1, g_B1);
    cudaGetSymbolAddress((void**)&B2, g_B2);
    cudaGetSymbolAddress((void**)&B3, g_B3);
    cudaGetSymbolAddress((void**)&Wh, g_Wh);
    cudaGetSymbolAddress((void**)&x1, g_x1);
    cudaGetSymbolAddress((void**)&x2, g_x2);
    cudaGetSymbolAddress((void**)&hb, g_h);
    cudaGetSymbolAddress((void**)&xp, g_xp);
    cudaGetSymbolAddress((void**)&ssrc, g_ssrc);
    cudaGetSymbolAddress((void**)&sdst, g_sdst);
    cudaGetSymbolAddress((void**)&srcI, g_srcI);
    cudaGetSymbolAddress((void**)&dstI, g_dstI);
    cudaGetSymbolAddress((void**)&cnt, g_cnt);
    cudaGetSymbolAddress((void**)&rowptr, g_rowptr);
    cudaGetSymbolAddress((void**)&cursor, g_cursor);
    cudaGetSymbolAddress((void**)&csrSrc, g_csrSrc);

    static int smem_set = 0;
    if (!smem_set) {
        cudaFuncSetAttribute(gemm_tf32, cudaFuncAttributeMaxDynamicSharedMemorySize,
                             GEMM_SMEM);
        smem_set = 1;
    }

    const int N = NN, E = NE;
    const int TB = 256;
    float* ss0 = ssrc;              float* sd0 = sdst;
    float* ss1 = ssrc + 6 * NN;     float* sd1 = sdst + 6 * NN;
    float* ss2 = ssrc + 12 * NN;    float* sd2 = sdst + 12 * NN;

    setup_k<<<(N * 64 + TB - 1) / TB, TB>>>(x, xp, cnt, ssrc, sdst);
    detect_k<<<1, 1024>>>(ei, N);
    convhist_k<<<(E + TB - 1) / TB, TB>>>(ei, srcI, dstI, cnt, E);
    scan_k<<<1, 1024>>>(cnt, rowptr, cursor, N);
    fill_k<<<(E + TB - 1) / TB, TB>>>(srcI, dstI, cursor, csrSrc, E);
    repackall_k<<<(64 * 1024 + 1024 * 1024 + 1024 * 768 + TB - 1) / TB, TB>>>(
        W1, W2, W3, B1, B2, B3);

    // ============ Layer 1: K=50->64, H=4, F=256 ============
    {
        int H = 4, F = 256, Ntot = 1024;
        dim3 g(Ntot / GBN, (N + GBM - 1) / GBM);
        gemm_tf32<<<g, 256, GEMM_SMEM>>>(N, Ntot, 64, xp, B1, Wh,
                                         a1, F, F, 2 * F, ss0, sd0);
        agg_k<<<((size_t)N * H * 32 + TB - 1) / TB, TB>>>(N, H, 2, Ntot, F, Ntot, F, 1,
                                                          rowptr, csrSrc, ss0, sd0, Wh,
                                                          nullptr, x1);
    }

    // ============ Layer 2: K=1024, H=4, F=256, skip ============
    {
        int H = 4, F = 256, Ntot = 1024;
        dim3 g(Ntot / GBN, (N + GBM - 1) / GBM);
        gemm_tf32<<<g, 256, GEMM_SMEM>>>(N, Ntot, 1024, x1, B2, Wh,
                                         a2, F, F, 2 * F, ss1, sd1);
        agg_k<<<((size_t)N * H * 32 + TB - 1) / TB, TB>>>(N, H, 2, Ntot, F, Ntot, F, 2,
                                                          rowptr, csrSrc, ss1, sd1, Wh,
                                                          x1, x2);
    }

    // ============ Layer 3: K=1024, H=6, F=121 (pad 128), mean heads ============
    {
        int H = 6, F = 121, FP = 128, Ntot = 768;
        dim3 g(Ntot / GBN, (N + GBM - 1) / GBM);
        gemm_tf32<<<g, 256, GEMM_SMEM>>>(N, Ntot, 1024, x2, B3, Wh,
                                         a3, F, FP, 2 * F, ss2, sd2);
        agg_k<<<((size_t)N * H * 32 + TB - 1) / TB, TB>>>(N, H, 1, Ntot, FP, Ntot, FP, 0,
                                                          rowptr, csrSrc, ss2, sd2, Wh,
                                                          nullptr, hb);
        final_k<<<(N * 121 + TB - 1) / TB, TB>>>(hb, out, N);
    }
}

// round 12
// speedup vs baseline: 1.0938x; 1.0938x over previous
#include <cuda_runtime.h>
#include <cstdint>
#include <cstddef>

#define NN 20000
#define NE 320000
#define ALPHA 0.2f

// ---------------- scratch (device globals; no allocation allowed) ------------
__device__ __align__(16) float g_B1[64 * 1024];
__device__ __align__(16) float g_B2[1024 * 1024];
__device__ __align__(16) float g_B3[1024 * 768];
__device__ __align__(16) float g_Wh[(size_t)NN * 1024];
__device__ __align__(16) float g_x1[(size_t)NN * 1024];
__device__ __align__(16) float g_x2[(size_t)NN * 1024];
__device__ __align__(16) float g_h[(size_t)NN * 1024];
__device__ __align__(16) float g_xp[(size_t)NN * 64];
__device__ __align__(16) float g_ssrc[3 * 6 * NN];
__device__ __align__(16) float g_sdst[3 * 6 * NN];
__device__ __align__(16) int g_srcI[NE];
__device__ __align__(16) int g_dstI[NE];
__device__ __align__(16) int g_cnt[NN];
__device__ __align__(16) int g_rowptr[NN + 4];
__device__ __align__(16) int g_cursor[NN];
__device__ __align__(16) int g_csrSrc[NE];
__device__ int g_is64;

// ---------------- helpers ----------------------------------------------------
__device__ __forceinline__ float eluf(float z) { return z > 0.f ? z : expm1f(z); }
__device__ __forceinline__ float lrelu(float v) { return v > 0.f ? v : ALPHA * v; }
__device__ __forceinline__ unsigned smem_u32(const void* p) {
    return (unsigned)__cvta_generic_to_shared(p);
}
__device__ __forceinline__ void cp16(unsigned dst, const void* src, int szbytes) {
    asm volatile("cp.async.cg.shared.global [%0], [%1], 16, %2;"
                 :: "r"(dst), "l"(src), "r"(szbytes));
}
__device__ __forceinline__ void cp_commit() { asm volatile("cp.async.commit_group;"); }
template <int NWAIT>
__device__ __forceinline__ void cp_wait() {
    asm volatile("cp.async.wait_group %0;" :: "n"(NWAIT));
}

// ---------------- setup kernels -----------------------------------------------
__global__ void detect_k(const void* __restrict__ ei, int N) {
    __shared__ int bad;
    if (threadIdx.x == 0) bad = 0;
    __syncthreads();
    long long v = ((const long long*)ei)[threadIdx.x];
    if (v < 0 || v >= N) bad = 1;
    __syncthreads();
    if (threadIdx.x == 0) g_is64 = !bad;
}
// zero cnt + score buffers, pad x -> xp, all in one grid
__global__ void setup_k(const float* __restrict__ x, float* __restrict__ xp,
                        int* __restrict__ cnt, float* __restrict__ ssrc,
                        float* __restrict__ sdst) {
    int i = blockIdx.x * blockDim.x + threadIdx.x;
    if (i < NN) cnt[i] = 0;
    if (i < 3 * 6 * NN) { ssrc[i] = 0.f; sdst[i] = 0.f; }
    if (i < NN * 64) {
        int n = i >> 6, c = i & 63;
        xp[i] = (c < 50) ? x[n * 50 + c] : 0.f;
    }
}
__global__ void convhist_k(const void* __restrict__ ei, int* __restrict__ s,
                           int* __restrict__ d, int* __restrict__ cnt, int E) {
    int i = blockIdx.x * blockDim.x + threadIdx.x;
    if (i >= E) return;
    int sv, dv;
    if (g_is64) {
        const long long* p = (const long long*)ei;
        sv = (int)p[i]; dv = (int)p[E + i];
    } else {
        const int* p = (const int*)ei;
        sv = p[i]; dv = p[E + i];
    }
    s[i] = sv; d[i] = dv;
    atomicAdd(&cnt[dv], 1);
}
// one-pass blocked scan: 1024 threads x 20 elements each
#define CPT 20
__global__ void scan_k(const int* __restrict__ cnt, int* __restrict__ rowptr,
                       int* __restrict__ cursor, int n) {
    __shared__ int sums[32];
    const int t = threadIdx.x;
    const int lane = t & 31, wid = t >> 5;
    const int base = t * CPT;
    int v[CPT];
    int tot = 0;
#pragma unroll
    for (int j = 0; j < CPT; j++) {
        v[j] = (base + j < n) ? cnt[base + j] : 0;
        tot += v[j];
    }
    int x = tot;
#pragma unroll
    for (int o = 1; o < 32; o <<= 1) {
        int y = __shfl_up_sync(0xffffffffu, x, o);
        if (lane >= o) x += y;
    }
    if (lane == 31) sums[wid] = x;
    __syncthreads();
    if (wid == 0) {
        int s = sums[lane];
#pragma unroll
        for (int o = 1; o < 32; o <<= 1) {
            int y = __shfl_up_sync(0xffffffffu, s, o);
            if (lane >= o) s += y;
        }
        sums[lane] = s;
    }
    __syncthreads();
    int run = (x - tot) + (wid ? sums[wid - 1] : 0);   // exclusive prefix
    if (t == 0) rowptr[0] = 0;
#pragma unroll
    for (int j = 0; j < CPT; j++) {
        int idx = base + j;
        if (idx < n) {
            cursor[idx] = run;
            run += v[j];
            rowptr[idx + 1] = run;
        }
    }
}
__global__ void fill_k(const int* __restrict__ src, const int* __restrict__ dst,
                       int* __restrict__ cursor, int* __restrict__ csrSrc, int E) {
    int i = blockIdx.x * blockDim.x + threadIdx.x;
    if (i >= E) return;
    int pos = atomicAdd(&cursor[dst[i]], 1);
    csrSrc[pos] = src[i];
}
// all three weight repacks in one launch
__global__ void repackall_k(const float* __restrict__ W1, const float* __restrict__ W2,
                            const float* __restrict__ W3, float* __restrict__ B1,
                            float* __restrict__ B2, float* __restrict__ B3) {
    const int T1 = 64 * 1024, T2 = 1024 * 1024, T3 = 1024 * 768;
    int i = blockIdx.x * blockDim.x + threadIdx.x;
    if (i < T1) {
        int k = i >> 10, rem = i & 1023, h = rem >> 8, f = rem & 255;
        B1[i] = (k < 50) ? W1[((size_t)h * 50 + k) * 256 + f] : 0.f;
    } else if (i < T1 + T2) {
        int j = i - T1;
        int k = j >> 10, rem = j & 1023, h = rem >> 8, f = rem & 255;
        B2[j] = W2[((size_t)h * 1024 + k) * 256 + f];
    } else if (i < T1 + T2 + T3) {
        int j = i - T1 - T2;
        int k = j / 768, rem = j - k * 768, h = rem >> 7, f = rem & 127;
        B3[j] = (f < 121) ? W3[((size_t)h * 1024 + k) * 121 + f] : 0.f;
    }
}

// ---------------- TF32 GEMM, GBK=16, 3-stage cp.async, fused scores -----------
#define GBM 128
#define GBN 128
#define GBK 16
#define APAD 20
#define BPAD 136
#define AS_WORDS (GBM * APAD)
#define BS_WORDS (GBK * BPAD)
#define STAGE_WORDS (AS_WORDS + BS_WORDS)
#define GEMM_SMEM (3 * STAGE_WORDS * 4)

__global__ __launch_bounds__(256) void gemm_tf32(int M, int N, int K,
                                                 const float* __restrict__ A,
                                                 const float* __restrict__ B,
                                                 float* __restrict__ C,
                                                 const float* __restrict__ aVec,
                                                 int F, int hs, int astride,
                                                 float* __restrict__ ssrc,
                                                 float* __restrict__ sdst) {
    extern __shared__ float sm[];

    const int tid = threadIdx.x;
    const int warp = tid >> 5;
    const int lane = tid & 31;
    const int g = lane >> 2;
    const int tig = lane & 3;
    const int wm = warp & 1;
    const int wn = warp >> 1;
    const int bm = blockIdx.y * GBM;
    const int bn = blockIdx.x * GBN;

    const int ar0 = tid >> 2, ac0 = (tid & 3) * 4;
    const int ar1 = (tid + 256) >> 2;
    const int bk0 = tid >> 5, bc0 = (tid & 31) * 4;
    const int bk1 = (tid + 256) >> 5;

    float acc[4][4][4];
#pragma unroll
    for (int mf = 0; mf < 4; mf++)
#pragma unroll
        for (int nf = 0; nf < 4; nf++)
#pragma unroll
            for (int r = 0; r < 4; r++) acc[mf][nf][r] = 0.f;

    const int KT = K / GBK;

    auto issue = [&](int kt, int stg) {
        float* As = sm + stg * STAGE_WORDS;
        float* Bs = As + AS_WORDS;
        const int k0 = kt * GBK;
        cp16(smem_u32(As + ar0 * APAD + ac0), A + (size_t)(bm + ar0) * K + k0 + ac0,
             (bm + ar0 < M) ? 16 : 0);
        cp16(smem_u32(As + ar1 * APAD + ac0), A + (size_t)(bm + ar1) * K + k0 + ac0,
             (bm + ar1 < M) ? 16 : 0);
        cp16(smem_u32(Bs + bk0 * BPAD + bc0), B + (size_t)(k0 + bk0) * N + bn + bc0, 16);
        cp16(smem_u32(Bs + bk1 * BPAD + bc0), B + (size_t)(k0 + bk1) * N + bn + bc0, 16);
    };

    issue(0, 0); cp_commit();
    if (KT > 1) issue(1, 1);
    cp_commit();

    int stg = 0, stg2 = (KT > 2) ? 2 : (KT == 2 ? 0 : 1);
    for (int kt = 0; kt < KT; kt++) {
        cp_wait<1>();
        __syncthreads();
        if (kt + 2 < KT) issue(kt + 2, stg2);
        cp_commit();

        const float* As = sm + stg * STAGE_WORDS;
        const float* Bs = As + AS_WORDS;
#pragma unroll
        for (int ks = 0; ks < 2; ks++) {
            const int kc = ks * 8;
            unsigned af[4][4], bf[4][2];
#pragma unroll
            for (int mf = 0; mf < 4; mf++) {
                int r = wm * 64 + mf * 16;
                af[mf][0] = __float_as_uint(As[(r + g) * APAD + kc + tig]);
                af[mf][1] = __float_as_uint(As[(r + g + 8) * APAD + kc + tig]);
                af[mf][2] = __float_as_uint(As[(r + g) * APAD + kc + tig + 4]);
                af[mf][3] = __float_as_uint(As[(r + g + 8) * APAD + kc + tig + 4]);
            }
#pragma unroll
            for (int nf = 0; nf < 4; nf++) {
                int c = wn * 32 + nf * 8 + g;
                bf[nf][0] = __float_as_uint(Bs[(kc + tig) * BPAD + c]);
                bf[nf][1] = __float_as_uint(Bs[(kc + tig + 4) * BPAD + c]);
            }
#pragma unroll
            for (int mf = 0; mf < 4; mf++)
#pragma unroll
                for (int nf = 0; nf < 4; nf++) {
                    asm volatile(
                        "mma.sync.aligned.m16n8k8.row.col.f32.tf32.tf32.f32 "
                        "{%0,%1,%2,%3}, {%4,%5,%6,%7}, {%8,%9}, {%0,%1,%2,%3};"
                        : "+f"(acc[mf][nf][0]), "+f"(acc[mf][nf][1]),
                          "+f"(acc[mf][nf][2]), "+f"(acc[mf][nf][3])
                        : "r"(af[mf][0]), "r"(af[mf][1]), "r"(af[mf][2]), "r"(af[mf][3]),
                          "r"(bf[nf][0]), "r"(bf[nf][1]));
                }
        }
        stg = (stg + 1 == 3) ? 0 : stg + 1;
        stg2 = (stg2 + 1 == 3) ? 0 : stg2 + 1;
    }

    // ---- store C ----
#pragma unroll
    for (int mf = 0; mf < 4; mf++) {
        int r0 = bm + wm * 64 + mf * 16 + g;
#pragma unroll
        for (int nf = 0; nf < 4; nf++) {
            int c0 = bn + wn * 32 + nf * 8 + tig * 2;
            if (r0 < M) {
                float2 v = make_float2(acc[mf][nf][0], acc[mf][nf][1]);
                *(float2*)(C + (size_t)r0 * N + c0) = v;
            }
            if (r0 + 8 < M) {
                float2 v = make_float2(acc[mf][nf][2], acc[mf][nf][3]);
                *(float2*)(C + (size_t)(r0 + 8) * N + c0) = v;
            }
        }
    }

    // ---- fused attention-score partial dot ----
    {
        const int h0 = bn / hs;
        const int cbase = bn % hs;
        const float* av = aVec + (size_t)h0 * astride;
        float as_[8], ad_[8];
#pragma unroll
        for (int nf = 0; nf < 4; nf++)
#pragma unroll
            for (int e = 0; e < 2; e++) {
                int cf = cbase + wn * 32 + nf * 8 + tig * 2 + e;
                bool ok = cf < F;
                as_[nf * 2 + e] = ok ? av[cf] : 0.f;
                ad_[nf * 2 + e] = ok ? av[F + cf] : 0.f;
            }
#pragma unroll
        for (int mf = 0; mf < 4; mf++) {
            float s0 = 0.f, d0 = 0.f, s1 = 0.f, d1 = 0.f;
#pragma unroll
            for (int nf = 0; nf < 4; nf++)
#pragma unroll
                for (int e = 0; e < 2; e++) {
                    int idx = nf * 2 + e;
                    s0 += acc[mf][nf][e] * as_[idx];
                    d0 += acc[mf][nf][e] * ad_[idx];
                    s1 += acc[mf][nf][2 + e] * as_[idx];
                    d1 += acc[mf][nf][2 + e] * ad_[idx];
                }
#pragma unroll
            for (int o = 1; o <= 2; o <<= 1) {
                s0 += __shfl_xor_sync(0xffffffffu, s0, o);
                d0 += __shfl_xor_sync(0xffffffffu, d0, o);
                s1 += __shfl_xor_sync(0xffffffffu, s1, o);
                d1 += __shfl_xor_sync(0xffffffffu, d1, o);
            }
            if (tig == 0) {
                int r0 = bm + wm * 64 + mf * 16 + g;
                if (r0 < M) {
                    atomicAdd(&ssrc[h0 * NN + r0], s0);
                    atomicAdd(&sdst[h0 * NN + r0], d0);
                }
                if (r0 + 8 < M) {
                    atomicAdd(&ssrc[h0 * NN + r0 + 8], s1);
                    atomicAdd(&sdst[h0 * NN + r0 + 8], d1);
                }
            }
        }
    }
}

// ---------------- fused online-softmax + gather aggregation + epilogue --------
__global__ void agg_k(int N, int H, int F4, int ld, int hs, int outld, int ouths,
                      int mode,
                      const int* __restrict__ rowptr, const int* __restrict__ csrSrc,
                      const float* __restrict__ ssrc, const float* __restrict__ sdst,
                      const float* __restrict__ Wh, const float* __restrict__ xskip,
                      float* __restrict__ out) {
    int gw = (blockIdx.x * blockDim.x + threadIdx.x) >> 5;
    if (gw >= N * H) return;
    int lane = threadIdx.x & 31;
    int d = gw / H, h = gw - d * H;
    int start = rowptr[d], end = rowptr[d + 1];
    float sd = sdst[h * N + d];
    const float* ss = ssrc + (size_t)h * N;

    float m = -1e30f, s = 0.f;
    for (int i = start + lane; i < end; i += 32) {
        float v = lrelu(ss[csrSrc[i]] + sd);
        if (v > m) { s = s * __expf(m - v) + 1.f; m = v; }
        else s += __expf(v - m);
    }
#pragma unroll
    for (int o = 16; o; o >>= 1) {
        float mo = __shfl_xor_sync(0xffffffffu, m, o);
        float so = __shfl_xor_sync(0xffffffffu, s, o);
        float M = fmaxf(m, mo);
        s = s * __expf(m - M) + so * __expf(mo - M);
        m = M;
    }
    float inv = 1.f / (s + 1e-16f);

    float4 a0 = make_float4(0.f, 0.f, 0.f, 0.f);
    float4 a1 = make_float4(0.f, 0.f, 0.f, 0.f);
#pragma unroll 2
    for (int i = start; i < end; i++) {
        int sidx = csrSrc[i];
        float w = __expf(lrelu(ss[sidx] + sd) - m) * inv;
        const float4* rp = (const float4*)(Wh + (size_t)sidx * ld + h * hs);
        float4 u = rp[lane];
        a0.x += w * u.x; a0.y += w * u.y; a0.z += w * u.z; a0.w += w * u.w;
        if (F4 == 2) {
            float4 u2 = rp[lane + 32];
            a1.x += w * u2.x; a1.y += w * u2.y; a1.z += w * u2.z; a1.w += w * u2.w;
        }
    }

    size_t obase = (size_t)d * outld + h * ouths;
    if (mode == 1) {
        a0.x = eluf(eluf(a0.x)); a0.y = eluf(eluf(a0.y));
        a0.z = eluf(eluf(a0.z)); a0.w = eluf(eluf(a0.w));
        a1.x = eluf(eluf(a1.x)); a1.y = eluf(eluf(a1.y));
        a1.z = eluf(eluf(a1.z)); a1.w = eluf(eluf(a1.w));
    } else if (mode == 2) {
        const float4* xp = (const float4*)(xskip + obase);
        float4 p0 = xp[lane];
        a0.x = eluf(eluf(a0.x) + p0.x); a0.y = eluf(eluf(a0.y) + p0.y);
        a0.z = eluf(eluf(a0.z) + p0.z); a0.w = eluf(eluf(a0.w) + p0.w);
        if (F4 == 2) {
            float4 p1 = xp[lane + 32];
            a1.x = eluf(eluf(a1.x) + p1.x); a1.y = eluf(eluf(a1.y) + p1.y);
            a1.z = eluf(eluf(a1.z) + p1.z); a1.w = eluf(eluf(a1.w) + p1.w);
        }
    }
    float4* op = (float4*)(out + obase);
    op[lane] = a0;
    if (F4 == 2) op[lane + 32] = a1;
}

// ---------------- final: mean over 6 heads + sigmoid --------------------------
__global__ void final_k(const float* __restrict__ h3, float* __restrict__ out, int N) {
    int i = blockIdx.x * blockDim.x + threadIdx.x;
    if (i >= N * 121) return;
    int n = i / 121, f = i - n * 121;
    const float* base = h3 + (size_t)n * 768 + f;
    float v = 0.f;
#pragma unroll
    for (int h = 0; h < 6; h++) v += base[h * 128];
    v *= (1.f / 6.f);
    out[i] = 1.f / (1.f + __expf(-v));
}

// ---------------- driver ------------------------------------------------------
extern "C" void kernel_launch(void* const* d_in, const int* in_sizes, int n_in,
                              void* d_out, int out_size) {
    const float* x = (const float*)d_in[0];
    const void* ei = d_in[1];
    const float* W1 = (const float*)d_in[2];
    const float* a1 = (const float*)d_in[3];
    const float* W2 = (const float*)d_in[4];
    const float* a2 = (const float*)d_in[5];
    const float* W3 = (const float*)d_in[6];
    const float* a3 = (const float*)d_in[7];
    float* out = (float*)d_out;

    float *B1, *B2, *B3, *Wh, *x1, *x2, *hb, *xp, *ssrc, *sdst;
    int *srcI, *dstI, *cnt, *rowptr, *cursor, *csrSrc;
    cudaGetSymbolAddress((void**)&B1, g_B1);
    cudaGetSymbolAddress((void**)&B2, g_B2);
    cudaGetSymbolAddress((void**)&B3, g_B3);
    cudaGetSymbolAddress((void**)&Wh, g_Wh);
    cudaGetSymbolAddress((void**)&x1, g_x1);
    cudaGetSymbolAddress((void**)&x2, g_x2);
    cudaGetSymbolAddress((void**)&hb, g_h);
    cudaGetSymbolAddress((void**)&xp, g_xp);
    cudaGetSymbolAddress((void**)&ssrc, g_ssrc);
    cudaGetSymbolAddress((void**)&sdst, g_sdst);
    cudaGetSymbolAddress((void**)&srcI, g_srcI);
    cudaGetSymbolAddress((void**)&dstI, g_dstI);
    cudaGetSymbolAddress((void**)&cnt, g_cnt);
    cudaGetSymbolAddress((void**)&rowptr, g_rowptr);
    cudaGetSymbolAddress((void**)&cursor, g_cursor);
    cudaGetSymbolAddress((void**)&csrSrc, g_csrSrc);

    static int inited = 0;
    static cudaStream_t s2;
    static cudaEvent_t evFork, evJoin;
    if (!inited) {
        cudaFuncSetAttribute(gemm_tf32, cudaFuncAttributeMaxDynamicSharedMemorySize,
                             GEMM_SMEM);
        cudaStreamCreateWithFlags(&s2, cudaStreamNonBlocking);
        cudaEventCreateWithFlags(&evFork, cudaEventDisableTiming);
        cudaEventCreateWithFlags(&evJoin, cudaEventDisableTiming);
        inited = 1;
    }

    const int N = NN, E = NE;
    const int TB = 256;
    float* ss0 = ssrc;              float* sd0 = sdst;
    float* ss1 = ssrc + 6 * NN;     float* sd1 = sdst + 6 * NN;
    float* ss2 = ssrc + 12 * NN;    float* sd2 = sdst + 12 * NN;

    // main stream: zero/pad (cnt needed by CSR branch), then fork
    setup_k<<<(N * 64 + TB - 1) / TB, TB>>>(x, xp, cnt, ssrc, sdst);
    cudaEventRecord(evFork, 0);
    cudaStreamWaitEvent(s2, evFork, 0);

    // CSR branch on s2 (only consumer is agg_k layer 1)
    detect_k<<<1, 1024, 0, s2>>>(ei, N);
    convhist_k<<<(E + TB - 1) / TB, TB, 0, s2>>>(ei, srcI, dstI, cnt, E);
    scan_k<<<1, 1024, 0, s2>>>(cnt, rowptr, cursor, N);
    fill_k<<<(E + TB - 1) / TB, TB, 0, s2>>>(srcI, dstI, cursor, csrSrc, E);
    cudaEventRecord(evJoin, s2);

    // main stream continues: weights + layer-1 GEMM (independent of CSR)
    repackall_k<<<(64 * 1024 + 1024 * 1024 + 1024 * 768 + TB - 1) / TB, TB>>>(
        W1, W2, W3, B1, B2, B3);

    // ============ Layer 1: K=50->64, H=4, F=256 ============
    {
        int H = 4, F = 256, Ntot = 1024;
        dim3 g(Ntot / GBN, (N + GBM - 1) / GBM);
        gemm_tf32<<<g, 256, GEMM_SMEM>>>(N, Ntot, 64, xp, B1, Wh,
                                         a1, F, F, 2 * F, ss0, sd0);
        cudaStreamWaitEvent(0, evJoin, 0);   // CSR ready before first agg
        agg_k<<<((size_t)N * H * 32 + TB - 1) / TB, TB>>>(N, H, 2, Ntot, F, Ntot, F, 1,
                                                          rowptr, csrSrc, ss0, sd0, Wh,
                                                          nullptr, x1);
    }

    // ============ Layer 2: K=1024, H=4, F=256, skip ============
    {
        int H = 4, F = 256, Ntot = 1024;
        dim3 g(Ntot / GBN, (N + GBM - 1) / GBM);
        gemm_tf32<<<g, 256, GEMM_SMEM>>>(N, Ntot, 1024, x1, B2, Wh,
                                         a2, F, F, 2 * F, ss1, sd1);
        agg_k<<<((size_t)N * H * 32 + TB - 1) / TB, TB>>>(N, H, 2, Ntot, F, Ntot, F, 2,
                                                          rowptr, csrSrc, ss1, sd1, Wh,
                                                          x1, x2);
    }

    // ============ Layer 3: K=1024, H=6, F=121 (pad 128), mean heads ============
    {
        int H = 6, F = 121, FP = 128, Ntot = 768;
        dim3 g(Ntot / GBN, (N + GBM - 1) / GBM);
        gemm_tf32<<<g, 256, GEMM_SMEM>>>(N, Ntot, 1024, x2, B3, Wh,
                                         a3, F, FP, 2 * F, ss2, sd2);
        agg_k<<<((size_t)N * H * 32 + TB - 1) / TB, TB>>>(N, H, 1, Ntot, FP, Ntot, FP, 0,
                                                          rowptr, csrSrc, ss2, sd2, Wh,
                                                          nullptr, hb);
        final_k<<<(N * 121 + TB - 1) / TB, TB>>>(hb, out, N);
    }
}